// round 1
// baseline (speedup 1.0000x reference)
#include <cuda_runtime.h>
#include <cstdint>

// Problem constants
#define BATCH  4
#define SEQ    4096
#define DMODEL 1024
#define NHEAD  16
#define HDIM   64
#define MROWS  (BATCH*SEQ)          // 16384
#define NQKV   (3*DMODEL)           // 3072

// Scratch (device globals: allocation-free)
__device__ float g_qkv[(size_t)MROWS * NQKV];   // 192 MB
__device__ float g_ao [(size_t)MROWS * DMODEL]; //  64 MB (already in the "swapaxes+reshape" scrambled layout)

// ---------------------------------------------------------------------------
// helpers
// ---------------------------------------------------------------------------
__device__ __forceinline__ float f2tf(float x) {
    uint32_t u;
    asm("cvt.rna.tf32.f32 %0, %1;" : "=r"(u) : "f"(x));
    return __uint_as_float(u);
}

__device__ __forceinline__ void mma8(float c[4], const float a[4], const float b[2]) {
    uint32_t A0 = __float_as_uint(a[0]), A1 = __float_as_uint(a[1]);
    uint32_t A2 = __float_as_uint(a[2]), A3 = __float_as_uint(a[3]);
    uint32_t B0 = __float_as_uint(b[0]), B1 = __float_as_uint(b[1]);
    asm volatile(
        "mma.sync.aligned.m16n8k8.row.col.f32.tf32.tf32.f32 "
        "{%0,%1,%2,%3}, {%4,%5,%6,%7}, {%8,%9}, {%0,%1,%2,%3};"
        : "+f"(c[0]), "+f"(c[1]), "+f"(c[2]), "+f"(c[3])
        : "r"(A0), "r"(A1), "r"(A2), "r"(A3), "r"(B0), "r"(B1));
}

// ---------------------------------------------------------------------------
// TF32 GEMM: C[M,Ncols] = A[M,K] * Bw[Ncols,K]^T (+ bias)
// BM=128, BN=128, BK=16, 256 threads (8 warps, 4x2), warp tile 32x64
// MODE 0: A = param, C = g_qkv (QKV projection, no bias)
// MODE 1: A = g_ao,  C = param + bias (output projection)
// ---------------------------------------------------------------------------
#define BM  128
#define BN  128
#define BK  16
#define LDT 20   // smem row stride (conflict-free fragment loads, 16B aligned rows)

template<int MODE>
__global__ __launch_bounds__(256)
void gemm_tf32(const float* __restrict__ Ain, const float* __restrict__ Bw,
               const float* __restrict__ bias, float* __restrict__ Cout,
               int K, int ldc)
{
    __shared__ float As[2][BM][LDT];
    __shared__ float Bs[2][BN][LDT];

    const float* __restrict__ A = (MODE == 0) ? Ain : g_ao;
    float* __restrict__ C       = (MODE == 0) ? g_qkv : Cout;

    const int tid  = threadIdx.x;
    const int warp = tid >> 5, lane = tid & 31;
    const int gp   = lane >> 2, tg = lane & 3;
    const int wm   = (warp & 3) * 32;
    const int wn   = (warp >> 2) * 64;
    const int bm   = blockIdx.y * BM;
    const int bn   = blockIdx.x * BN;

    const int lrow = tid >> 2;   // 0..63
    const int lc4  = tid & 3;    // float4 column within BK

    float acc[2][8][4];
    #pragma unroll
    for (int i = 0; i < 2; i++)
        #pragma unroll
        for (int j = 0; j < 8; j++)
            #pragma unroll
            for (int k = 0; k < 4; k++) acc[i][j][k] = 0.f;

    float4 ra[2], rb[2];
    const int nkt = K / BK;

    // prologue load tile 0
    #pragma unroll
    for (int i = 0; i < 2; i++) {
        ra[i] = *reinterpret_cast<const float4*>(&A [(size_t)(bm + lrow + 64*i)*K + lc4*4]);
        rb[i] = *reinterpret_cast<const float4*>(&Bw[(size_t)(bn + lrow + 64*i)*K + lc4*4]);
    }
    #pragma unroll
    for (int i = 0; i < 2; i++) {
        float4 a = ra[i];
        a.x=f2tf(a.x); a.y=f2tf(a.y); a.z=f2tf(a.z); a.w=f2tf(a.w);
        *reinterpret_cast<float4*>(&As[0][lrow + 64*i][lc4*4]) = a;
        float4 b = rb[i];
        b.x=f2tf(b.x); b.y=f2tf(b.y); b.z=f2tf(b.z); b.w=f2tf(b.w);
        *reinterpret_cast<float4*>(&Bs[0][lrow + 64*i][lc4*4]) = b;
    }
    __syncthreads();

    for (int kt = 0; kt < nkt; kt++) {
        const int cur = kt & 1;
        const bool has_next = (kt + 1 < nkt);
        if (has_next) {
            #pragma unroll
            for (int i = 0; i < 2; i++) {
                ra[i] = *reinterpret_cast<const float4*>(&A [(size_t)(bm + lrow + 64*i)*K + (kt+1)*BK + lc4*4]);
                rb[i] = *reinterpret_cast<const float4*>(&Bw[(size_t)(bn + lrow + 64*i)*K + (kt+1)*BK + lc4*4]);
            }
        }
        #pragma unroll
        for (int ks = 0; ks < 2; ks++) {
            const int c0 = ks*8 + tg, c1 = c0 + 4;
            float a[2][4], b[8][2];
            #pragma unroll
            for (int mt = 0; mt < 2; mt++) {
                const int r0 = wm + mt*16 + gp;
                a[mt][0] = As[cur][r0  ][c0];
                a[mt][1] = As[cur][r0+8][c0];
                a[mt][2] = As[cur][r0  ][c1];
                a[mt][3] = As[cur][r0+8][c1];
            }
            #pragma unroll
            for (int nt = 0; nt < 8; nt++) {
                const int nn = wn + nt*8 + gp;
                b[nt][0] = Bs[cur][nn][c0];
                b[nt][1] = Bs[cur][nn][c1];
            }
            #pragma unroll
            for (int mt = 0; mt < 2; mt++)
                #pragma unroll
                for (int nt = 0; nt < 8; nt++)
                    mma8(acc[mt][nt], a[mt], b[nt]);
        }
        if (has_next) {
            const int nxt = cur ^ 1;
            #pragma unroll
            for (int i = 0; i < 2; i++) {
                float4 a = ra[i];
                a.x=f2tf(a.x); a.y=f2tf(a.y); a.z=f2tf(a.z); a.w=f2tf(a.w);
                *reinterpret_cast<float4*>(&As[nxt][lrow + 64*i][lc4*4]) = a;
                float4 b = rb[i];
                b.x=f2tf(b.x); b.y=f2tf(b.y); b.z=f2tf(b.z); b.w=f2tf(b.w);
                *reinterpret_cast<float4*>(&Bs[nxt][lrow + 64*i][lc4*4]) = b;
            }
        }
        __syncthreads();
    }

    // epilogue
    #pragma unroll
    for (int mt = 0; mt < 2; mt++) {
        #pragma unroll
        for (int nt = 0; nt < 8; nt++) {
            const int col = bn + wn + nt*8 + 2*tg;
            float bx = 0.f, by = 0.f;
            if (MODE == 1) {
                float2 bv = *reinterpret_cast<const float2*>(&bias[col]);
                bx = bv.x; by = bv.y;
            }
            #pragma unroll
            for (int rr = 0; rr < 2; rr++) {
                const int row = bm + wm + mt*16 + gp + rr*8;
                float v0 = acc[mt][nt][rr*2 + 0] + bx;
                float v1 = acc[mt][nt][rr*2 + 1] + by;
                *reinterpret_cast<float2*>(&C[(size_t)row*ldc + col]) = make_float2(v0, v1);
            }
        }
    }
}

// ---------------------------------------------------------------------------
// Per-token head attention (the einsum is over HEADS, not sequence!).
// One warp per token. q,k,v: [16 heads][64 dims] each, from g_qkv row.
// S = q k^T (16x16, scaled), softmax over g, O = P v (16x64).
// Output written directly in the reference's swapaxes(1,2).reshape layout:
//   row i = h*256 + (n>>4), col j = (n&15)*64 + hd
// ---------------------------------------------------------------------------
#define AWARPS 8
#define ATTN_SMEM_FLOATS (AWARPS * (3*16*68 + 16*20))   // 28672 floats = 114688 B

__global__ __launch_bounds__(AWARPS*32)
void attn_tf32(float* __restrict__ dummy)
{
    extern __shared__ float sm[];
    const int warp = threadIdx.x >> 5, lane = threadIdx.x & 31;
    const int gp = lane >> 2, tg = lane & 3;

    float* wsm = sm + warp * (3*16*68 + 16*20);
    float (*Qs)[68] = reinterpret_cast<float(*)[68]>(wsm);
    float (*Ks)[68] = reinterpret_cast<float(*)[68]>(wsm + 1088);
    float (*Vs)[68] = reinterpret_cast<float(*)[68]>(wsm + 2176);
    float (*Ps)[20] = reinterpret_cast<float(*)[20]>(wsm + 3264);
    (void)dummy;

    const int token = blockIdx.x * AWARPS + warp;
    const float* base = g_qkv + (size_t)token * NQKV;
    const float scale = 0.125f;   // HD^-0.5

    // load q,k,v (each 1024 floats) into smem, tf32-rounded; q pre-scaled
    #pragma unroll
    for (int j = 0; j < 8; j++) {
        const int c4 = lane + j*32;        // float4 index 0..255
        const int h  = c4 >> 4;
        const int d4 = (c4 & 15) * 4;
        float4 q = *reinterpret_cast<const float4*>(base + c4*4);
        q.x=f2tf(q.x*scale); q.y=f2tf(q.y*scale); q.z=f2tf(q.z*scale); q.w=f2tf(q.w*scale);
        *reinterpret_cast<float4*>(&Qs[h][d4]) = q;
        float4 k = *reinterpret_cast<const float4*>(base + 1024 + c4*4);
        k.x=f2tf(k.x); k.y=f2tf(k.y); k.z=f2tf(k.z); k.w=f2tf(k.w);
        *reinterpret_cast<float4*>(&Ks[h][d4]) = k;
        float4 v = *reinterpret_cast<const float4*>(base + 2048 + c4*4);
        v.x=f2tf(v.x); v.y=f2tf(v.y); v.z=f2tf(v.z); v.w=f2tf(v.w);
        *reinterpret_cast<float4*>(&Vs[h][d4]) = v;
    }
    __syncwarp();

    // S = Q K^T : m16 x n16 (2 tiles) x k64 (8 steps)
    float s[2][4] = {{0.f,0.f,0.f,0.f},{0.f,0.f,0.f,0.f}};
    #pragma unroll
    for (int ks = 0; ks < 8; ks++) {
        const int c0 = ks*8 + tg, c1 = c0 + 4;
        float a[4] = { Qs[gp][c0], Qs[gp+8][c0], Qs[gp][c1], Qs[gp+8][c1] };
        #pragma unroll
        for (int nt = 0; nt < 2; nt++) {
            float b[2] = { Ks[nt*8+gp][c0], Ks[nt*8+gp][c1] };
            mma8(s[nt], a, b);
        }
    }

    // softmax over g (all 16 cols present -> exact, no online pass)
    float m0 = fmaxf(fmaxf(s[0][0], s[0][1]), fmaxf(s[1][0], s[1][1]));
    float m1 = fmaxf(fmaxf(s[0][2], s[0][3]), fmaxf(s[1][2], s[1][3]));
    m0 = fmaxf(m0, __shfl_xor_sync(0xffffffffu, m0, 1));
    m0 = fmaxf(m0, __shfl_xor_sync(0xffffffffu, m0, 2));
    m1 = fmaxf(m1, __shfl_xor_sync(0xffffffffu, m1, 1));
    m1 = fmaxf(m1, __shfl_xor_sync(0xffffffffu, m1, 2));
    #pragma unroll
    for (int nt = 0; nt < 2; nt++) {
        s[nt][0] = __expf(s[nt][0] - m0);
        s[nt][1] = __expf(s[nt][1] - m0);
        s[nt][2] = __expf(s[nt][2] - m1);
        s[nt][3] = __expf(s[nt][3] - m1);
    }
    float l0 = s[0][0] + s[0][1] + s[1][0] + s[1][1];
    float l1 = s[0][2] + s[0][3] + s[1][2] + s[1][3];
    l0 += __shfl_xor_sync(0xffffffffu, l0, 1);
    l0 += __shfl_xor_sync(0xffffffffu, l0, 2);
    l1 += __shfl_xor_sync(0xffffffffu, l1, 1);
    l1 += __shfl_xor_sync(0xffffffffu, l1, 2);
    const float r0 = 1.f / l0, r1 = 1.f / l1;

    // write normalized P (tf32-rounded) for A-fragment reload
    #pragma unroll
    for (int nt = 0; nt < 2; nt++) {
        *reinterpret_cast<float2*>(&Ps[gp  ][nt*8 + 2*tg]) =
            make_float2(f2tf(s[nt][0]*r0), f2tf(s[nt][1]*r0));
        *reinterpret_cast<float2*>(&Ps[gp+8][nt*8 + 2*tg]) =
            make_float2(f2tf(s[nt][2]*r1), f2tf(s[nt][3]*r1));
    }
    __syncwarp();

    // O = P V : m16 x n64 (8 tiles) x k16 (2 steps)
    float o[8][4];
    #pragma unroll
    for (int nt = 0; nt < 8; nt++)
        #pragma unroll
        for (int k = 0; k < 4; k++) o[nt][k] = 0.f;
    #pragma unroll
    for (int ks = 0; ks < 2; ks++) {
        const int c0 = ks*8 + tg, c1 = c0 + 4;
        float a[4] = { Ps[gp][c0], Ps[gp+8][c0], Ps[gp][c1], Ps[gp+8][c1] };
        #pragma unroll
        for (int nt = 0; nt < 8; nt++) {
            float b[2] = { Vs[c0][nt*8+gp], Vs[c1][nt*8+gp] };
            mma8(o[nt], a, b);
        }
    }

    // scatter into scrambled proj-input layout
    const int bidx = token >> 12;
    const int n    = token & 4095;
    const int colb = (n & 15) * 64;
    #pragma unroll
    for (int rr = 0; rr < 2; rr++) {
        const int h = gp + rr*8;
        const size_t rowg = (size_t)(bidx*4096 + h*256 + (n >> 4)) * 1024;
        #pragma unroll
        for (int nt = 0; nt < 8; nt++) {
            const int hd = nt*8 + 2*tg;
            *reinterpret_cast<float2*>(&g_ao[rowg + colb + hd]) =
                make_float2(o[nt][rr*2], o[nt][rr*2+1]);
        }
    }
}

// ---------------------------------------------------------------------------
// launcher
// ---------------------------------------------------------------------------
extern "C" void kernel_launch(void* const* d_in, const int* in_sizes, int n_in,
                              void* d_out, int out_size)
{
    (void)in_sizes; (void)n_in; (void)out_size;
    const float* x      = (const float*)d_in[0];  // [4,4096,1024]
    const float* w_qkv  = (const float*)d_in[1];  // [3072,1024]
    const float* w_proj = (const float*)d_in[2];  // [1024,1024]
    const float* b_proj = (const float*)d_in[3];  // [1024]
    float* out = (float*)d_out;                   // [4,4096,1024]

    // 1) QKV projection: g_qkv = x @ w_qkv^T
    gemm_tf32<0><<<dim3(NQKV/BN, MROWS/BM), 256>>>(x, w_qkv, nullptr, nullptr,
                                                   DMODEL, NQKV);

    // 2) per-token head attention -> g_ao (scrambled layout)
    cudaFuncSetAttribute(attn_tf32, cudaFuncAttributeMaxDynamicSharedMemorySize,
                         ATTN_SMEM_FLOATS * (int)sizeof(float));
    attn_tf32<<<MROWS/AWARPS, AWARPS*32, ATTN_SMEM_FLOATS * sizeof(float)>>>(nullptr);

    // 3) output projection: out = g_ao @ w_proj^T + b_proj
    gemm_tf32<1><<<dim3(DMODEL/BN, MROWS/BM), 256>>>(nullptr, w_proj, b_proj, out,
                                                     DMODEL, DMODEL);
}